// round 9
// baseline (speedup 1.0000x reference)
#include <cuda_runtime.h>
#include <math.h>

#define BLK 128
#define NJ 12

typedef unsigned long long u64;

// h3 scratch: element-packed u64 = (h3_elemA, h3_elemB), feature-major.
// 64 features x 262144 pair-threads x 8B = 128 MiB.
#define NT_MAX 262144
__device__ u64 g_h3[64 * NT_MAX];

__device__ __forceinline__ u64 fma2(u64 a, u64 b, u64 c) {
    u64 d; asm("fma.rn.f32x2 %0, %1, %2, %3;" : "=l"(d) : "l"(a), "l"(b), "l"(c)); return d;
}
__device__ __forceinline__ u64 mul2(u64 a, u64 b) {
    u64 d; asm("mul.rn.f32x2 %0, %1, %2;" : "=l"(d) : "l"(a), "l"(b)); return d;
}
__device__ __forceinline__ u64 add2(u64 a, u64 b) {
    u64 d; asm("add.rn.f32x2 %0, %1, %2;" : "=l"(d) : "l"(a), "l"(b)); return d;
}
__device__ __forceinline__ u64 pack2(float lo, float hi) {
    u64 d; asm("mov.b64 %0, {%1, %2};" : "=l"(d) : "f"(lo), "f"(hi)); return d;
}
__device__ __forceinline__ void unpack2(u64 a, float& lo, float& hi) {
    asm("mov.b64 {%0, %1}, %2;" : "=f"(lo), "=f"(hi) : "l"(a));
}
__device__ __forceinline__ float hsum_relu(u64 acc, float bias) {
    float lo, hi; unpack2(acc, lo, hi);
    return fmaxf(bias + lo + hi, 0.0f);
}

#define ONE2  0x3F8000003F800000ULL
#define ZERO2 0ULL

// Dot-packed layer for TWO elements (plain weights, shared loads).
template<int OUT, int IN>
__device__ __forceinline__ void dotlayer(const float* __restrict__ sW,
                                         const float* __restrict__ sB,
                                         const u64* __restrict__ hA,
                                         const u64* __restrict__ hB,
                                         u64* __restrict__ outA,
                                         u64* __restrict__ outB) {
    #pragma unroll
    for (int o = 0; o < OUT; o += 2) {
        u64 aA0 = ZERO2, aA1 = ZERO2, bA0 = ZERO2, bA1 = ZERO2;
        u64 aB0 = ZERO2, aB1 = ZERO2, bB0 = ZERO2, bB1 = ZERO2;
        const float* r0 = sW + o * IN;
        const float* r1 = r0 + IN;
        #pragma unroll
        for (int k = 0; k < IN; k += 4) {
            const ulonglong2 w0 = *reinterpret_cast<const ulonglong2*>(r0 + k);
            const ulonglong2 w1 = *reinterpret_cast<const ulonglong2*>(r1 + k);
            const u64 hAa = hA[k / 2], hAb = hA[k / 2 + 1];
            const u64 hBa = hB[k / 2], hBb = hB[k / 2 + 1];
            aA0 = fma2(w0.x, hAa, aA0);  aA1 = fma2(w0.y, hAb, aA1);
            aB0 = fma2(w0.x, hBa, aB0);  aB1 = fma2(w0.y, hBb, aB1);
            bA0 = fma2(w1.x, hAa, bA0);  bA1 = fma2(w1.y, hAb, bA1);
            bB0 = fma2(w1.x, hBa, bB0);  bB1 = fma2(w1.y, hBb, bB1);
        }
        const float bo = sB[o], bo1 = sB[o + 1];
        outA[o / 2] = pack2(hsum_relu(add2(aA0, aA1), bo),
                            hsum_relu(add2(bA0, bA1), bo1));
        outB[o / 2] = pack2(hsum_relu(add2(aB0, aB1), bo),
                            hsum_relu(add2(bB0, bB1), bo1));
    }
}

// ======================= Kernel A: L1 -> L2 -> L3 =======================
__global__ __launch_bounds__(BLK, 4)
void fk_a(const float* __restrict__ mc,
          const float* __restrict__ W1, const float* __restrict__ b1,
          const float* __restrict__ W2, const float* __restrict__ b2,
          const float* __restrict__ W3, const float* __restrict__ b3,
          int B, int NT)
{
    __shared__ __align__(16) float sW1[16 * 4];
    __shared__ __align__(16) float sW2[32 * 16];
    __shared__ __align__(16) float sW3[64 * 32];
    __shared__ float sB1[16], sB2[32], sB3[64];

    const int tid = threadIdx.x;
    for (int t = tid; t < 16 * 4;  t += BLK) sW1[t] = W1[t];
    for (int t = tid; t < 32 * 16; t += BLK) sW2[t] = W2[t];
    for (int t = tid; t < 64 * 32; t += BLK) sW3[t] = W3[t];
    for (int t = tid; t < 16; t += BLK) sB1[t] = b1[t];
    for (int t = tid; t < 32; t += BLK) sB2[t] = b2[t];
    for (int t = tid; t < 64; t += BLK) sB3[t] = b3[t];
    __syncthreads();

    const int g  = blockIdx.x * BLK + tid;       // pair-thread id
    const int i0 = blockIdx.x * (2 * BLK) + tid;
    if (i0 >= B) return;
    int i1 = i0 + BLK;
    if (i1 >= B) i1 = B - 1;

    const float4 a0 = reinterpret_cast<const float4*>(mc)[i0];
    const float4 a1 = reinterpret_cast<const float4*>(mc)[i1];
    u64 xA[2] = { pack2(a0.x, a0.y), pack2(a0.z, a0.w) };
    u64 xB[2] = { pack2(a1.x, a1.y), pack2(a1.z, a1.w) };

    u64 h1A[8],  h1B[8];  dotlayer<16, 4 >(sW1, sB1, xA,  xB,  h1A, h1B);
    u64 h2A[16], h2B[16]; dotlayer<32, 16>(sW2, sB2, h1A, h1B, h2A, h2B);

    // L3: stream h3 feature pairs, element-packed, straight to global scratch.
    #pragma unroll
    for (int c = 0; c < 64; c += 2) {
        u64 aA0 = ZERO2, aA1 = ZERO2, bA0 = ZERO2, bA1 = ZERO2;
        u64 aB0 = ZERO2, aB1 = ZERO2, bB0 = ZERO2, bB1 = ZERO2;
        const float* r0 = sW3 + c * 32;
        const float* r1 = r0 + 32;
        #pragma unroll
        for (int k = 0; k < 32; k += 4) {
            const ulonglong2 w0 = *reinterpret_cast<const ulonglong2*>(r0 + k);
            const ulonglong2 w1 = *reinterpret_cast<const ulonglong2*>(r1 + k);
            const u64 hAa = h2A[k / 2], hAb = h2A[k / 2 + 1];
            const u64 hBa = h2B[k / 2], hBb = h2B[k / 2 + 1];
            aA0 = fma2(w0.x, hAa, aA0);  aA1 = fma2(w0.y, hAb, aA1);
            aB0 = fma2(w0.x, hBa, aB0);  aB1 = fma2(w0.y, hBb, aB1);
            bA0 = fma2(w1.x, hAa, bA0);  bA1 = fma2(w1.y, hAb, bA1);
            bB0 = fma2(w1.x, hBa, bB0);  bB1 = fma2(w1.y, hBb, bB1);
        }
        const float bc = sB3[c], bc1 = sB3[c + 1];
        const u64 hp0 = pack2(hsum_relu(add2(aA0, aA1), bc),
                              hsum_relu(add2(aB0, aB1), bc));
        const u64 hp1 = pack2(hsum_relu(add2(bA0, bA1), bc1),
                              hsum_relu(add2(bB0, bB1), bc1));
        g_h3[(size_t)c       * NT + g] = hp0;   // coalesced STG.64
        g_h3[(size_t)(c + 1) * NT + g] = hp1;
    }
}

// =================== Kernel B: L4 -> L5 -> SE(3) chain ===================
__global__ __launch_bounds__(BLK, 4)
void fk_b(const float* __restrict__ W4, const float* __restrict__ b4,
          const float* __restrict__ W5, const float* __restrict__ b5,
          const float* __restrict__ twist,
          const float* __restrict__ init_p,
          const float* __restrict__ init_rpy,
          float* __restrict__ out, int B, int NT)
{
    // W4 transposed [k][o], duplicated pairs for element-packed accumulate
    __shared__ __align__(16) u64 sW4D[64 * 32];
    __shared__ __align__(16) float sW5[12 * 32];
    __shared__ float sB4[32], sB5[12];
    __shared__ u64 sjwn[NJ];
    __shared__ u64 sjru[NJ][3], sjKru[NJ][3], sjK2ru[NJ][3];
    __shared__ u64 sjK[NJ][9], sjK2[NJ][9];
    __shared__ u64 sT0[12];

    const int tid = threadIdx.x;

    for (int t = tid; t < 32 * 64; t += BLK) {
        const int o = t / 64, k = t % 64;
        float w = W4[t];
        sW4D[k * 32 + o] = pack2(w, w);
    }
    for (int t = tid; t < 12 * 32; t += BLK) sW5[t] = W5[t];
    for (int t = tid; t < 32; t += BLK) sB4[t] = b4[t];
    for (int t = tid; t < 12; t += BLK) sB5[t] = b5[t];

    if (tid < NJ) {
        const float* tw = twist + tid * 6;
        float rx = tw[0], ry = tw[1], rz = tw[2];
        float wx = tw[3], wy = tw[4], wz = tw[5];
        float wn  = sqrtf(wx * wx + wy * wy + wz * wz + 1e-12f);
        float inv = 1.0f / wn;
        float ux = wx * inv, uy = wy * inv, uz = wz * inv;
        float rux = rx * inv, ruy = ry * inv, ruz = rz * inv;
        float K[9] = { 0.f, -uz,  uy,
                       uz,  0.f, -ux,
                      -uy,  ux,  0.f };
        float K2[9];
        #pragma unroll
        for (int a = 0; a < 3; a++)
            #pragma unroll
            for (int bb = 0; bb < 3; bb++)
                K2[a*3+bb] = K[a*3+0]*K[0*3+bb] + K[a*3+1]*K[1*3+bb] + K[a*3+2]*K[2*3+bb];
        sjwn[tid] = pack2(wn, wn);
        sjru[tid][0] = pack2(rux, rux); sjru[tid][1] = pack2(ruy, ruy); sjru[tid][2] = pack2(ruz, ruz);
        #pragma unroll
        for (int a = 0; a < 3; a++) {
            float kr  = K[a*3+0]*rux  + K[a*3+1]*ruy  + K[a*3+2]*ruz;
            float k2r = K2[a*3+0]*rux + K2[a*3+1]*ruy + K2[a*3+2]*ruz;
            sjKru[tid][a]  = pack2(kr, kr);
            sjK2ru[tid][a] = pack2(k2r, k2r);
        }
        #pragma unroll
        for (int e = 0; e < 9; e++) {
            sjK[tid][e]  = pack2(K[e], K[e]);
            sjK2[tid][e] = pack2(K2[e], K2[e]);
        }
    }
    if (tid == 32) {
        float r = init_rpy[0], p = init_rpy[1], y = init_rpy[2];
        float cr = cosf(r), sr = sinf(r);
        float cp = cosf(p), sp = sinf(p);
        float cy = cosf(y), sy = sinf(y);
        float T0[12] = {
            cy*cp,  cy*sp*sr - sy*cr,  cy*sp*cr + sy*sr,  init_p[0],
            sy*cp,  sy*sp*sr + cy*cr,  sy*sp*cr - cy*sr,  init_p[1],
            -sp,    cp*sr,             cp*cr,             init_p[2] };
        #pragma unroll
        for (int e = 0; e < 12; e++) sT0[e] = pack2(T0[e], T0[e]);
    }
    __syncthreads();

    const int g  = blockIdx.x * BLK + tid;
    const int i0 = blockIdx.x * (2 * BLK) + tid;
    if (i0 >= B) return;
    int i1 = i0 + BLK;
    if (i1 >= B) i1 = B - 1;

    // ---- L4: element-packed accumulate over streamed h3 ----
    u64 acc4[32];
    #pragma unroll
    for (int o = 0; o < 32; o++) acc4[o] = ZERO2;

    #pragma unroll
    for (int c = 0; c < 64; c += 2) {
        const u64 hp0 = __ldg(&g_h3[(size_t)c       * NT + g]);  // coalesced LDG.64
        const u64 hp1 = __ldg(&g_h3[(size_t)(c + 1) * NT + g]);
        const u64* rA = sW4D + c * 32;
        const u64* rB = rA + 32;
        #pragma unroll
        for (int o = 0; o < 32; o += 2) {
            const ulonglong2 w0 = *reinterpret_cast<const ulonglong2*>(rA + o);
            const ulonglong2 w1 = *reinterpret_cast<const ulonglong2*>(rB + o);
            acc4[o]     = fma2(w0.x, hp0, acc4[o]);
            acc4[o + 1] = fma2(w0.y, hp0, acc4[o + 1]);
            acc4[o]     = fma2(w1.x, hp1, acc4[o]);
            acc4[o + 1] = fma2(w1.y, hp1, acc4[o + 1]);
        }
    }

    // collapse L4 -> per-element feature pairs
    u64 h4A[16], h4B[16];
    #pragma unroll
    for (int o = 0; o < 32; o += 2) {
        float a0f, b0f, a1f, b1f;
        unpack2(acc4[o],     a0f, b0f);
        unpack2(acc4[o + 1], a1f, b1f);
        const float bo = sB4[o], bo1 = sB4[o + 1];
        h4A[o / 2] = pack2(fmaxf(a0f + bo, 0.f), fmaxf(a1f + bo1, 0.f));
        h4B[o / 2] = pack2(fmaxf(b0f + bo, 0.f), fmaxf(b1f + bo1, 0.f));
    }

    // L5 -> element-packed q
    u64 qv[NJ];
    #pragma unroll
    for (int o = 0; o < 12; o += 2) {
        u64 aA0 = ZERO2, aA1 = ZERO2, bA0 = ZERO2, bA1 = ZERO2;
        u64 aB0 = ZERO2, aB1 = ZERO2, bB0 = ZERO2, bB1 = ZERO2;
        const float* r0 = sW5 + o * 32;
        const float* r1 = r0 + 32;
        #pragma unroll
        for (int k = 0; k < 32; k += 4) {
            const ulonglong2 w0 = *reinterpret_cast<const ulonglong2*>(r0 + k);
            const ulonglong2 w1 = *reinterpret_cast<const ulonglong2*>(r1 + k);
            const u64 hAa = h4A[k / 2], hAb = h4A[k / 2 + 1];
            const u64 hBa = h4B[k / 2], hBb = h4B[k / 2 + 1];
            aA0 = fma2(w0.x, hAa, aA0);  aA1 = fma2(w0.y, hAb, aA1);
            aB0 = fma2(w0.x, hBa, aB0);  aB1 = fma2(w0.y, hBb, aB1);
            bA0 = fma2(w1.x, hAa, bA0);  bA1 = fma2(w1.y, hAb, bA1);
            bB0 = fma2(w1.x, hBa, bB0);  bB1 = fma2(w1.y, hBb, bB1);
        }
        const float bo = sB5[o], bo1 = sB5[o + 1];
        qv[o]     = pack2(hsum_relu(add2(aA0, aA1), bo),
                          hsum_relu(add2(aB0, aB1), bo));
        qv[o + 1] = pack2(hsum_relu(add2(bA0, bA1), bo1),
                          hsum_relu(add2(bB0, bB1), bo1));
    }

    // ---- element-packed SE(3) chain ----
    u64 T[12] = { ONE2, ZERO2, ZERO2, ZERO2,
                  ZERO2, ONE2, ZERO2, ZERO2,
                  ZERO2, ZERO2, ONE2, ZERO2 };
    #pragma unroll
    for (int j = 0; j < NJ; j++) {
        const u64 th2 = mul2(qv[j], sjwn[j]);
        float th0, th1; unpack2(th2, th0, th1);
        float s0, co0, s1, co1;
        __sincosf(th0, &s0, &co0);
        __sincosf(th1, &s1, &co1);
        const u64 s2 = pack2(s0, s1);
        const u64 c2 = pack2(1.0f - co0, 1.0f - co1);
        const u64 t2 = pack2(th0 - s0, th1 - s1);

        u64 R[9];
        #pragma unroll
        for (int e = 0; e < 9; e++) {
            const u64 d = (e == 0 || e == 4 || e == 8) ? ONE2 : ZERO2;
            R[e] = fma2(s2, sjK[j][e], fma2(c2, sjK2[j][e], d));
        }
        const u64 p0 = fma2(th2, sjru[j][0], fma2(c2, sjKru[j][0], mul2(t2, sjK2ru[j][0])));
        const u64 p1 = fma2(th2, sjru[j][1], fma2(c2, sjKru[j][1], mul2(t2, sjK2ru[j][1])));
        const u64 p2 = fma2(th2, sjru[j][2], fma2(c2, sjKru[j][2], mul2(t2, sjK2ru[j][2])));

        u64 N[12];
        #pragma unroll
        for (int r = 0; r < 3; r++) {
            const u64 a0r = T[r*4+0], a1r = T[r*4+1], a2r = T[r*4+2], a3r = T[r*4+3];
            N[r*4+0] = fma2(a0r, R[0], fma2(a1r, R[3], mul2(a2r, R[6])));
            N[r*4+1] = fma2(a0r, R[1], fma2(a1r, R[4], mul2(a2r, R[7])));
            N[r*4+2] = fma2(a0r, R[2], fma2(a1r, R[5], mul2(a2r, R[8])));
            N[r*4+3] = fma2(a0r, p0,  fma2(a1r, p1,  fma2(a2r, p2, a3r)));
        }
        #pragma unroll
        for (int e = 0; e < 12; e++) T[e] = N[e];
    }

    float4* op0 = reinterpret_cast<float4*>(out + (size_t)i0 * 16);
    float4* op1 = reinterpret_cast<float4*>(out + (size_t)i1 * 16);
    #pragma unroll
    for (int r = 0; r < 3; r++) {
        const u64 a0r = T[r*4+0], a1r = T[r*4+1], a2r = T[r*4+2], a3r = T[r*4+3];
        const u64 vx = fma2(a0r, sT0[0], fma2(a1r, sT0[4], mul2(a2r, sT0[8])));
        const u64 vy = fma2(a0r, sT0[1], fma2(a1r, sT0[5], mul2(a2r, sT0[9])));
        const u64 vz = fma2(a0r, sT0[2], fma2(a1r, sT0[6], mul2(a2r, sT0[10])));
        const u64 vw = fma2(a0r, sT0[3], fma2(a1r, sT0[7], fma2(a2r, sT0[11], a3r)));
        float4 r0, r1;
        unpack2(vx, r0.x, r1.x);
        unpack2(vy, r0.y, r1.y);
        unpack2(vz, r0.z, r1.z);
        unpack2(vw, r0.w, r1.w);
        op0[r] = r0;
        op1[r] = r1;
    }
    op0[3] = make_float4(0.f, 0.f, 0.f, 1.f);
    op1[3] = make_float4(0.f, 0.f, 0.f, 1.f);
}

extern "C" void kernel_launch(void* const* d_in, const int* in_sizes, int n_in,
                              void* d_out, int out_size)
{
    const float* mc   = (const float*)d_in[0];
    const float* W1   = (const float*)d_in[1];
    const float* b1   = (const float*)d_in[2];
    const float* W2   = (const float*)d_in[3];
    const float* b2   = (const float*)d_in[4];
    const float* W3   = (const float*)d_in[5];
    const float* b3   = (const float*)d_in[6];
    const float* W4   = (const float*)d_in[7];
    const float* b4   = (const float*)d_in[8];
    const float* W5   = (const float*)d_in[9];
    const float* b5   = (const float*)d_in[10];
    const float* tw   = (const float*)d_in[11];
    const float* ip   = (const float*)d_in[12];
    const float* irpy = (const float*)d_in[13];
    float* out = (float*)d_out;

    const int B = in_sizes[0] / 4;
    const int grid = (B + 2 * BLK - 1) / (2 * BLK);
    const int NT = grid * BLK;   // pair-thread count (fits NT_MAX for B=524288)

    fk_a<<<grid, BLK>>>(mc, W1, b1, W2, b2, W3, b3, B, NT);
    fk_b<<<grid, BLK>>>(W4, b4, W5, b5, tw, ip, irpy, out, B, NT);
}

// round 10
// speedup vs baseline: 1.0998x; 1.0998x over previous
#include <cuda_runtime.h>
#include <math.h>

#define BLK 128
#define NJ 12

typedef unsigned long long u64;

__device__ __forceinline__ u64 fma2(u64 a, u64 b, u64 c) {
    u64 d; asm("fma.rn.f32x2 %0, %1, %2, %3;" : "=l"(d) : "l"(a), "l"(b), "l"(c)); return d;
}
__device__ __forceinline__ u64 add2(u64 a, u64 b) {
    u64 d; asm("add.rn.f32x2 %0, %1, %2;" : "=l"(d) : "l"(a), "l"(b)); return d;
}
__device__ __forceinline__ u64 pack2(float lo, float hi) {
    u64 d; asm("mov.b64 %0, {%1, %2};" : "=l"(d) : "f"(lo), "f"(hi)); return d;
}
__device__ __forceinline__ void unpack2(u64 a, float& lo, float& hi) {
    asm("mov.b64 {%0, %1}, %2;" : "=f"(lo), "=f"(hi) : "l"(a));
}
__device__ __forceinline__ float hsum(u64 acc) {
    float lo, hi; unpack2(acc, lo, hi); return lo + hi;
}
__device__ __forceinline__ float hsum_relu(u64 acc, float bias) {
    float lo, hi; unpack2(acc, lo, hi);
    return fmaxf(bias + lo + hi, 0.0f);
}

#define ZERO2 0ULL

// Dot-packed layer for two elements (plain weights in shared, feature-pair
// activations). One LDS.128 = 4 weights -> 4 FFMA2 (2 per element).
template<int OUT, int IN>
__device__ __forceinline__ void dotlayer(const float* __restrict__ sW,
                                         const float* __restrict__ sB,
                                         const u64* __restrict__ hA,
                                         const u64* __restrict__ hB,
                                         u64* __restrict__ outA,
                                         u64* __restrict__ outB) {
    #pragma unroll
    for (int o = 0; o < OUT; o += 2) {
        u64 aA0 = ZERO2, aA1 = ZERO2, bA0 = ZERO2, bA1 = ZERO2;
        u64 aB0 = ZERO2, aB1 = ZERO2, bB0 = ZERO2, bB1 = ZERO2;
        const float* r0 = sW + o * IN;
        const float* r1 = r0 + IN;
        #pragma unroll
        for (int k = 0; k < IN; k += 4) {
            const ulonglong2 w0 = *reinterpret_cast<const ulonglong2*>(r0 + k);
            const ulonglong2 w1 = *reinterpret_cast<const ulonglong2*>(r1 + k);
            const u64 hAa = hA[k / 2], hAb = hA[k / 2 + 1];
            const u64 hBa = hB[k / 2], hBb = hB[k / 2 + 1];
            aA0 = fma2(w0.x, hAa, aA0);  aA1 = fma2(w0.y, hAb, aA1);
            aB0 = fma2(w0.x, hBa, aB0);  aB1 = fma2(w0.y, hBb, aB1);
            bA0 = fma2(w1.x, hAa, bA0);  bA1 = fma2(w1.y, hAb, bA1);
            bB0 = fma2(w1.x, hBa, bB0);  bB1 = fma2(w1.y, hBb, bB1);
        }
        const float bo = sB[o], bo1 = sB[o + 1];
        outA[o / 2] = pack2(hsum_relu(add2(aA0, aA1), bo),
                            hsum_relu(add2(bA0, bA1), bo1));
        outB[o / 2] = pack2(hsum_relu(add2(aB0, aB1), bo),
                            hsum_relu(add2(bB0, bB1), bo1));
    }
}

__global__ __launch_bounds__(BLK, 5)
void fk_kernel(const float* __restrict__ mc,
               const float* __restrict__ W1, const float* __restrict__ b1,
               const float* __restrict__ W2, const float* __restrict__ b2,
               const float* __restrict__ W3, const float* __restrict__ b3,
               const float* __restrict__ W4, const float* __restrict__ b4,
               const float* __restrict__ W5, const float* __restrict__ b5,
               const float* __restrict__ twist,
               const float* __restrict__ init_p,
               const float* __restrict__ init_rpy,
               float* __restrict__ out, int B, int NP)
{
    __shared__ __align__(16) float sW1[16 * 4];
    __shared__ __align__(16) float sW2[32 * 16];
    __shared__ __align__(16) float sW3[64 * 32];
    __shared__ __align__(16) u64   sW4D[64 * 32];  // [k][o] dup pairs
    __shared__ __align__(16) float sW5[12 * 32];
    __shared__ float sB1[16], sB2[32], sB3[64], sB4[32], sB5[12];
    __shared__ float jwn[NJ];
    __shared__ float jru[NJ][3], jKru[NJ][3], jK2ru[NJ][3];
    __shared__ float jK[NJ][9], jK2[NJ][9];
    __shared__ float sT0[12];

    const int tid = threadIdx.x;

    for (int t = tid; t < 16 * 4;  t += BLK) sW1[t] = W1[t];
    for (int t = tid; t < 32 * 16; t += BLK) sW2[t] = W2[t];
    for (int t = tid; t < 64 * 32; t += BLK) sW3[t] = W3[t];
    for (int t = tid; t < 12 * 32; t += BLK) sW5[t] = W5[t];
    for (int t = tid; t < 32 * 64; t += BLK) {
        const int o = t / 64, k = t % 64;
        float w = W4[t];
        sW4D[k * 32 + o] = pack2(w, w);
    }
    for (int t = tid; t < 16; t += BLK) sB1[t] = b1[t];
    for (int t = tid; t < 32; t += BLK) sB2[t] = b2[t];
    for (int t = tid; t < 64; t += BLK) sB3[t] = b3[t];
    for (int t = tid; t < 32; t += BLK) sB4[t] = b4[t];
    for (int t = tid; t < 12; t += BLK) sB5[t] = b5[t];

    if (tid < NJ) {
        const float* tw = twist + tid * 6;
        float rx = tw[0], ry = tw[1], rz = tw[2];
        float wx = tw[3], wy = tw[4], wz = tw[5];
        float wn  = sqrtf(wx * wx + wy * wy + wz * wz + 1e-12f);
        float inv = 1.0f / wn;
        float ux = wx * inv, uy = wy * inv, uz = wz * inv;
        float rux = rx * inv, ruy = ry * inv, ruz = rz * inv;
        float K[9] = { 0.f, -uz,  uy,
                       uz,  0.f, -ux,
                      -uy,  ux,  0.f };
        float K2[9];
        #pragma unroll
        for (int a = 0; a < 3; a++)
            #pragma unroll
            for (int bb = 0; bb < 3; bb++)
                K2[a*3+bb] = K[a*3+0]*K[0*3+bb] + K[a*3+1]*K[1*3+bb] + K[a*3+2]*K[2*3+bb];
        jwn[tid] = wn;
        jru[tid][0] = rux; jru[tid][1] = ruy; jru[tid][2] = ruz;
        #pragma unroll
        for (int a = 0; a < 3; a++) {
            jKru[tid][a]  = K[a*3+0]*rux  + K[a*3+1]*ruy  + K[a*3+2]*ruz;
            jK2ru[tid][a] = K2[a*3+0]*rux + K2[a*3+1]*ruy + K2[a*3+2]*ruz;
        }
        #pragma unroll
        for (int e = 0; e < 9; e++) { jK[tid][e] = K[e]; jK2[tid][e] = K2[e]; }
    }
    if (tid == 32) {
        float r = init_rpy[0], p = init_rpy[1], y = init_rpy[2];
        float cr = cosf(r), sr = sinf(r);
        float cp = cosf(p), sp = sinf(p);
        float cy = cosf(y), sy = sinf(y);
        sT0[0] = cy*cp;  sT0[1] = cy*sp*sr - sy*cr;  sT0[2]  = cy*sp*cr + sy*sr;  sT0[3]  = init_p[0];
        sT0[4] = sy*cp;  sT0[5] = sy*sp*sr + cy*cr;  sT0[6]  = sy*sp*cr - cy*sr;  sT0[7]  = init_p[1];
        sT0[8] = -sp;    sT0[9] = cp*sr;             sT0[10] = cp*cr;             sT0[11] = init_p[2];
    }
    __syncthreads();

    // lane-pair cooperation: lanes l and l^16 share one element pair.
    const int warp = tid >> 5;
    const int lane = tid & 31;
    const int lp   = lane & 15;          // pair slot within warp
    const int role = lane >> 4;          // 0: lower k/o half, 1: upper
    const int kb   = role * 16;          // this lane's k/o slice base

    int P = blockIdx.x * 64 + warp * 16 + lp;   // pair id
    if (P >= NP) P = NP - 1;                    // duplicate-safe clamp
    const int eA = P;
    int eB = P + NP; if (eB >= B) eB = B - 1;

    const float4 xa = reinterpret_cast<const float4*>(mc)[eA];
    const float4 xb = reinterpret_cast<const float4*>(mc)[eB];
    u64 xA[2] = { pack2(xa.x, xa.y), pack2(xa.z, xa.w) };
    u64 xB[2] = { pack2(xb.x, xb.y), pack2(xb.z, xb.w) };

    // L1 full (duplicated across roles — tiny)
    u64 h1A[8], h1B[8];
    dotlayer<16, 4>(sW1, sB1, xA, xB, h1A, h1B);

    // L2: only this lane's 16-output slice (rows kb..kb+15)
    u64 h2A[8], h2B[8];
    dotlayer<16, 16>(sW2 + kb * 16, sB2 + kb, h1A, h1B, h2A, h2B);

    // ---- fused L3 (k-split, shfl-combined) -> L4 (o-split scatter) ----
    u64 acc[16];
    #pragma unroll
    for (int o = 0; o < 16; o++) acc[o] = ZERO2;

    #pragma unroll
    for (int c0 = 0; c0 < 64; c0 += 4) {
        float myA[4], myB[4];
        #pragma unroll
        for (int cc = 0; cc < 4; cc++) {
            const float* row = sW3 + (c0 + cc) * 32 + kb;  // this lane's k-slice
            u64 pA0 = ZERO2, pA1 = ZERO2, pB0 = ZERO2, pB1 = ZERO2;
            #pragma unroll
            for (int k = 0; k < 16; k += 4) {
                const ulonglong2 w = *reinterpret_cast<const ulonglong2*>(row + k);
                pA0 = fma2(w.x, h2A[k / 2],     pA0);
                pA1 = fma2(w.y, h2A[k / 2 + 1], pA1);
                pB0 = fma2(w.x, h2B[k / 2],     pB0);
                pB1 = fma2(w.y, h2B[k / 2 + 1], pB1);
            }
            myA[cc] = hsum(add2(pA0, pA1));
            myB[cc] = hsum(add2(pB0, pB1));
        }
        // combine k-halves with partner lane (independent shfls, pipelined)
        u64 hp[4];
        #pragma unroll
        for (int cc = 0; cc < 4; cc++) {
            const float oA = __shfl_xor_sync(0xffffffffu, myA[cc], 16);
            const float oB = __shfl_xor_sync(0xffffffffu, myB[cc], 16);
            const float bias = sB3[c0 + cc];
            hp[cc] = pack2(fmaxf(myA[cc] + oA + bias, 0.0f),
                           fmaxf(myB[cc] + oB + bias, 0.0f));
        }
        // scatter into this lane's 16-output slice of L4 (elem-packed acc)
        #pragma unroll
        for (int cc = 0; cc < 4; cc++) {
            const u64* r = sW4D + (c0 + cc) * 32 + kb;
            #pragma unroll
            for (int o = 0; o < 16; o += 2) {
                const ulonglong2 w = *reinterpret_cast<const ulonglong2*>(r + o);
                acc[o]     = fma2(w.x, hp[cc], acc[o]);
                acc[o + 1] = fma2(w.y, hp[cc], acc[o + 1]);
            }
        }
    }

    // collapse L4 slice -> per-element feature pairs (this lane's h4 slice)
    u64 h4A[8], h4B[8];
    #pragma unroll
    for (int o = 0; o < 16; o += 2) {
        float a0, b0, a1, b1;
        unpack2(acc[o],     a0, b0);
        unpack2(acc[o + 1], a1, b1);
        const float bo = sB4[kb + o], bo1 = sB4[kb + o + 1];
        h4A[o / 2] = pack2(fmaxf(a0 + bo, 0.f), fmaxf(a1 + bo1, 0.f));
        h4B[o / 2] = pack2(fmaxf(b0 + bo, 0.f), fmaxf(b1 + bo1, 0.f));
    }

    // L5: each lane sums over its own h4 slice, combine via shfl
    float qe[NJ];
    #pragma unroll
    for (int j = 0; j < NJ; j++) {
        const float* row = sW5 + j * 32 + kb;
        u64 pA0 = ZERO2, pA1 = ZERO2, pB0 = ZERO2, pB1 = ZERO2;
        #pragma unroll
        for (int k = 0; k < 16; k += 4) {
            const ulonglong2 w = *reinterpret_cast<const ulonglong2*>(row + k);
            pA0 = fma2(w.x, h4A[k / 2],     pA0);
            pA1 = fma2(w.y, h4A[k / 2 + 1], pA1);
            pB0 = fma2(w.x, h4B[k / 2],     pB0);
            pB1 = fma2(w.y, h4B[k / 2 + 1], pB1);
        }
        const u64 mine = pack2(hsum(add2(pA0, pA1)), hsum(add2(pB0, pB1)));
        const u64 other = __shfl_xor_sync(0xffffffffu, mine, 16);
        const u64 s = add2(mine, other);
        float qA, qB; unpack2(s, qA, qB);
        qA = fmaxf(qA + sB5[j], 0.0f);
        qB = fmaxf(qB + sB5[j], 0.0f);
        qe[j] = role ? qB : qA;
    }

    // ---- scalar SE(3) chain on this lane's own element ----
    const int e = role ? eB : eA;
    float T[12] = {1.f,0.f,0.f,0.f,  0.f,1.f,0.f,0.f,  0.f,0.f,1.f,0.f};
    #pragma unroll
    for (int j = 0; j < NJ; j++) {
        const float th = qe[j] * jwn[j];
        float s, co;
        __sincosf(th, &s, &co);
        const float c = 1.0f - co;
        const float t = th - s;

        float R[9];
        #pragma unroll
        for (int k = 0; k < 9; k++) {
            const float d = (k == 0 || k == 4 || k == 8) ? 1.0f : 0.0f;
            R[k] = fmaf(s, jK[j][k], fmaf(c, jK2[j][k], d));
        }
        const float p0 = fmaf(th, jru[j][0], fmaf(c, jKru[j][0], t * jK2ru[j][0]));
        const float p1 = fmaf(th, jru[j][1], fmaf(c, jKru[j][1], t * jK2ru[j][1]));
        const float p2 = fmaf(th, jru[j][2], fmaf(c, jKru[j][2], t * jK2ru[j][2]));

        float N[12];
        #pragma unroll
        for (int r = 0; r < 3; r++) {
            const float a0 = T[r*4+0], a1 = T[r*4+1], a2 = T[r*4+2], a3 = T[r*4+3];
            N[r*4+0] = fmaf(a0, R[0], fmaf(a1, R[3], a2 * R[6]));
            N[r*4+1] = fmaf(a0, R[1], fmaf(a1, R[4], a2 * R[7]));
            N[r*4+2] = fmaf(a0, R[2], fmaf(a1, R[5], a2 * R[8]));
            N[r*4+3] = fmaf(a0, p0,  fmaf(a1, p1,  fmaf(a2, p2, a3)));
        }
        #pragma unroll
        for (int k = 0; k < 12; k++) T[k] = N[k];
    }

    float4* op = reinterpret_cast<float4*>(out + (size_t)e * 16);
    #pragma unroll
    for (int r = 0; r < 3; r++) {
        const float a0 = T[r*4+0], a1 = T[r*4+1], a2 = T[r*4+2], a3 = T[r*4+3];
        float4 v;
        v.x = fmaf(a0, sT0[0], fmaf(a1, sT0[4], a2 * sT0[8]));
        v.y = fmaf(a0, sT0[1], fmaf(a1, sT0[5], a2 * sT0[9]));
        v.z = fmaf(a0, sT0[2], fmaf(a1, sT0[6], a2 * sT0[10]));
        v.w = fmaf(a0, sT0[3], fmaf(a1, sT0[7], fmaf(a2, sT0[11], a3)));
        op[r] = v;
    }
    op[3] = make_float4(0.f, 0.f, 0.f, 1.f);
}

extern "C" void kernel_launch(void* const* d_in, const int* in_sizes, int n_in,
                              void* d_out, int out_size)
{
    const float* mc   = (const float*)d_in[0];
    const float* W1   = (const float*)d_in[1];
    const float* b1   = (const float*)d_in[2];
    const float* W2   = (const float*)d_in[3];
    const float* b2   = (const float*)d_in[4];
    const float* W3   = (const float*)d_in[5];
    const float* b3   = (const float*)d_in[6];
    const float* W4   = (const float*)d_in[7];
    const float* b4   = (const float*)d_in[8];
    const float* W5   = (const float*)d_in[9];
    const float* b5   = (const float*)d_in[10];
    const float* tw   = (const float*)d_in[11];
    const float* ip   = (const float*)d_in[12];
    const float* irpy = (const float*)d_in[13];
    float* out = (float*)d_out;

    const int B  = in_sizes[0] / 4;
    const int NP = (B + 1) / 2;                 // element pairs
    const int grid = (NP + 63) / 64;            // 64 pairs per block (128 thr)
    fk_kernel<<<grid, BLK>>>(mc, W1, b1, W2, b2, W3, b3, W4, b4, W5, b5,
                             tw, ip, irpy, out, B, NP);
}

// round 11
// speedup vs baseline: 1.3414x; 1.2196x over previous
#include <cuda_runtime.h>
#include <math.h>

#define BLK 128
#define NJ 12

typedef unsigned long long u64;

__device__ __forceinline__ u64 fma2(u64 a, u64 b, u64 c) {
    u64 d; asm("fma.rn.f32x2 %0, %1, %2, %3;" : "=l"(d) : "l"(a), "l"(b), "l"(c)); return d;
}
__device__ __forceinline__ u64 mul2(u64 a, u64 b) {
    u64 d; asm("mul.rn.f32x2 %0, %1, %2;" : "=l"(d) : "l"(a), "l"(b)); return d;
}
__device__ __forceinline__ u64 add2(u64 a, u64 b) {
    u64 d; asm("add.rn.f32x2 %0, %1, %2;" : "=l"(d) : "l"(a), "l"(b)); return d;
}
__device__ __forceinline__ u64 pack2(float lo, float hi) {
    u64 d; asm("mov.b64 %0, {%1, %2};" : "=l"(d) : "f"(lo), "f"(hi)); return d;
}
__device__ __forceinline__ void unpack2(u64 a, float& lo, float& hi) {
    asm("mov.b64 {%0, %1}, %2;" : "=f"(lo), "=f"(hi) : "l"(a));
}
__device__ __forceinline__ float hsum_relu(u64 acc, float bias) {
    float lo, hi; unpack2(acc, lo, hi);
    return fmaxf(bias + lo + hi, 0.0f);
}
__device__ __forceinline__ u64 relu2(u64 a) {
    float lo, hi; unpack2(a, lo, hi);
    return pack2(fmaxf(lo, 0.0f), fmaxf(hi, 0.0f));
}

#define ONE2  0x3F8000003F800000ULL
#define ZERO2 0ULL

// Dot-packed layer for TWO elements (plain weights, LDS.128 shared by both).
template<int OUT, int IN>
__device__ __forceinline__ void dotlayer(const float* __restrict__ sW,
                                         const float* __restrict__ sB,
                                         const u64* __restrict__ hA,
                                         const u64* __restrict__ hB,
                                         u64* __restrict__ outA,
                                         u64* __restrict__ outB) {
    #pragma unroll
    for (int o = 0; o < OUT; o += 2) {
        u64 aA0 = ZERO2, aA1 = ZERO2, bA0 = ZERO2, bA1 = ZERO2;
        u64 aB0 = ZERO2, aB1 = ZERO2, bB0 = ZERO2, bB1 = ZERO2;
        const float* r0 = sW + o * IN;
        const float* r1 = r0 + IN;
        #pragma unroll
        for (int k = 0; k < IN; k += 4) {
            const ulonglong2 w0 = *reinterpret_cast<const ulonglong2*>(r0 + k);
            const ulonglong2 w1 = *reinterpret_cast<const ulonglong2*>(r1 + k);
            const u64 hAa = hA[k / 2], hAb = hA[k / 2 + 1];
            const u64 hBa = hB[k / 2], hBb = hB[k / 2 + 1];
            aA0 = fma2(w0.x, hAa, aA0);  aA1 = fma2(w0.y, hAb, aA1);
            aB0 = fma2(w0.x, hBa, aB0);  aB1 = fma2(w0.y, hBb, aB1);
            bA0 = fma2(w1.x, hAa, bA0);  bA1 = fma2(w1.y, hAb, bA1);
            bB0 = fma2(w1.x, hBa, bB0);  bB1 = fma2(w1.y, hBb, bB1);
        }
        const float bo = sB[o], bo1 = sB[o + 1];
        outA[o / 2] = pack2(hsum_relu(add2(aA0, aA1), bo),
                            hsum_relu(add2(bA0, bA1), bo1));
        outB[o / 2] = pack2(hsum_relu(add2(aB0, aB1), bo),
                            hsum_relu(add2(bB0, bB1), bo1));
    }
}

__global__ __launch_bounds__(BLK, 3)
void fk_kernel(const float* __restrict__ mc,
               const float* __restrict__ W1, const float* __restrict__ b1,
               const float* __restrict__ W2, const float* __restrict__ b2,
               const float* __restrict__ W3, const float* __restrict__ b3,
               const float* __restrict__ W4, const float* __restrict__ b4,
               const float* __restrict__ W5, const float* __restrict__ b5,
               const float* __restrict__ twist,
               const float* __restrict__ init_p,
               const float* __restrict__ init_rpy,
               float* __restrict__ out, int B)
{
    __shared__ __align__(16) float sW1[16 * 4];
    __shared__ __align__(16) float sW2[32 * 16];
    __shared__ __align__(16) float sW3[64 * 32];
    __shared__ __align__(16) float sW4T[64 * 32];  // PLAIN transposed [k][o]
    __shared__ __align__(16) float sW5[12 * 32];
    __shared__ float sB1[16], sB2[32], sB3[64];
    __shared__ __align__(8) float sB4[32];
    __shared__ float sB5[12];
    // chain constants, duplicated pairs
    __shared__ u64 sjwn[NJ];
    __shared__ u64 sjru[NJ][3], sjKru[NJ][3], sjK2ru[NJ][3];
    __shared__ u64 sjK[NJ][9], sjK2[NJ][9];
    __shared__ u64 sT0[12];

    const int tid = threadIdx.x;

    for (int t = tid; t < 16 * 4;  t += BLK) sW1[t] = W1[t];
    for (int t = tid; t < 32 * 16; t += BLK) sW2[t] = W2[t];
    for (int t = tid; t < 64 * 32; t += BLK) sW3[t] = W3[t];
    for (int t = tid; t < 12 * 32; t += BLK) sW5[t] = W5[t];
    for (int t = tid; t < 32 * 64; t += BLK) {
        const int o = t / 64, k = t % 64;     // W4 row-major [o][k]
        sW4T[k * 32 + o] = W4[t];
    }
    for (int t = tid; t < 16; t += BLK) sB1[t] = b1[t];
    for (int t = tid; t < 32; t += BLK) sB2[t] = b2[t];
    for (int t = tid; t < 64; t += BLK) sB3[t] = b3[t];
    for (int t = tid; t < 32; t += BLK) sB4[t] = b4[t];
    for (int t = tid; t < 12; t += BLK) sB5[t] = b5[t];

    if (tid < NJ) {
        const float* tw = twist + tid * 6;
        float rx = tw[0], ry = tw[1], rz = tw[2];
        float wx = tw[3], wy = tw[4], wz = tw[5];
        float wn  = sqrtf(wx * wx + wy * wy + wz * wz + 1e-12f);
        float inv = 1.0f / wn;
        float ux = wx * inv, uy = wy * inv, uz = wz * inv;
        float rux = rx * inv, ruy = ry * inv, ruz = rz * inv;
        float K[9] = { 0.f, -uz,  uy,
                       uz,  0.f, -ux,
                      -uy,  ux,  0.f };
        float K2[9];
        #pragma unroll
        for (int a = 0; a < 3; a++)
            #pragma unroll
            for (int bb = 0; bb < 3; bb++)
                K2[a*3+bb] = K[a*3+0]*K[0*3+bb] + K[a*3+1]*K[1*3+bb] + K[a*3+2]*K[2*3+bb];
        sjwn[tid] = pack2(wn, wn);
        sjru[tid][0] = pack2(rux, rux); sjru[tid][1] = pack2(ruy, ruy); sjru[tid][2] = pack2(ruz, ruz);
        #pragma unroll
        for (int a = 0; a < 3; a++) {
            float kr  = K[a*3+0]*rux  + K[a*3+1]*ruy  + K[a*3+2]*ruz;
            float k2r = K2[a*3+0]*rux + K2[a*3+1]*ruy + K2[a*3+2]*ruz;
            sjKru[tid][a]  = pack2(kr, kr);
            sjK2ru[tid][a] = pack2(k2r, k2r);
        }
        #pragma unroll
        for (int e = 0; e < 9; e++) {
            sjK[tid][e]  = pack2(K[e], K[e]);
            sjK2[tid][e] = pack2(K2[e], K2[e]);
        }
    }
    if (tid == 32) {
        float r = init_rpy[0], p = init_rpy[1], y = init_rpy[2];
        float cr = cosf(r), sr = sinf(r);
        float cp = cosf(p), sp = sinf(p);
        float cy = cosf(y), sy = sinf(y);
        float T0[12] = {
            cy*cp,  cy*sp*sr - sy*cr,  cy*sp*cr + sy*sr,  init_p[0],
            sy*cp,  sy*sp*sr + cy*cr,  sy*sp*cr - cy*sr,  init_p[1],
            -sp,    cp*sr,             cp*cr,             init_p[2] };
        #pragma unroll
        for (int e = 0; e < 12; e++) sT0[e] = pack2(T0[e], T0[e]);
    }
    __syncthreads();

    const int base = blockIdx.x * (2 * BLK);
    const int i0 = base + tid;
    if (i0 >= B) return;
    int i1 = i0 + BLK;
    if (i1 >= B) i1 = B - 1;   // duplicate-safe

    const float4 a0 = reinterpret_cast<const float4*>(mc)[i0];
    const float4 a1 = reinterpret_cast<const float4*>(mc)[i1];
    u64 xA[2] = { pack2(a0.x, a0.y), pack2(a0.z, a0.w) };
    u64 xB[2] = { pack2(a1.x, a1.y), pack2(a1.z, a1.w) };

    u64 h1A[8],  h1B[8];  dotlayer<16, 4 >(sW1, sB1, xA,  xB,  h1A, h1B);
    u64 h2A[16], h2B[16]; dotlayer<32, 16>(sW2, sB2, h1A, h1B, h2A, h2B);

    // ---- fused L3 -> L4 ----
    // L4 accumulators FEATURE-PACKED per element: accA[i] = (out_2i, out_2i+1)
    // so L4 uses plain contiguous weight pairs (shared load, both elements)
    // against duplicated scalar activations (2 cheap MOVs per feature).
    u64 accA[16], accB[16];
    #pragma unroll
    for (int o = 0; o < 16; o++) { accA[o] = ZERO2; accB[o] = ZERO2; }

    #pragma unroll
    for (int c = 0; c < 64; c += 2) {
        // h3 features c, c+1 for both elements (dot-packed over h2)
        u64 aA0 = ZERO2, aA1 = ZERO2, bA0 = ZERO2, bA1 = ZERO2;
        u64 aB0 = ZERO2, aB1 = ZERO2, bB0 = ZERO2, bB1 = ZERO2;
        const float* r0 = sW3 + c * 32;
        const float* r1 = r0 + 32;
        #pragma unroll
        for (int k = 0; k < 32; k += 4) {
            const ulonglong2 w0 = *reinterpret_cast<const ulonglong2*>(r0 + k);
            const ulonglong2 w1 = *reinterpret_cast<const ulonglong2*>(r1 + k);
            const u64 hAa = h2A[k / 2], hAb = h2A[k / 2 + 1];
            const u64 hBa = h2B[k / 2], hBb = h2B[k / 2 + 1];
            aA0 = fma2(w0.x, hAa, aA0);  aA1 = fma2(w0.y, hAb, aA1);
            aB0 = fma2(w0.x, hBa, aB0);  aB1 = fma2(w0.y, hBb, aB1);
            bA0 = fma2(w1.x, hAa, bA0);  bA1 = fma2(w1.y, hAb, bA1);
            bB0 = fma2(w1.x, hBa, bB0);  bB1 = fma2(w1.y, hBb, bB1);
        }
        const float bc = sB3[c], bc1 = sB3[c + 1];
        const float vA0 = hsum_relu(add2(aA0, aA1), bc);
        const float vA1 = hsum_relu(add2(bA0, bA1), bc1);
        const float vB0 = hsum_relu(add2(aB0, aB1), bc);
        const float vB1 = hsum_relu(add2(bB0, bB1), bc1);
        const u64 dA0 = pack2(vA0, vA0), dA1 = pack2(vA1, vA1);
        const u64 dB0 = pack2(vB0, vB0), dB1 = pack2(vB1, vB1);

        // scatter: plain W4T rows c, c+1 (4 weights per LDS.128, shared A/B)
        const float* wr0 = sW4T + c * 32;
        const float* wr1 = wr0 + 32;
        #pragma unroll
        for (int o = 0; o < 32; o += 4) {
            const ulonglong2 w0 = *reinterpret_cast<const ulonglong2*>(wr0 + o);
            const ulonglong2 w1 = *reinterpret_cast<const ulonglong2*>(wr1 + o);
            accA[o / 2]     = fma2(w0.x, dA0, accA[o / 2]);
            accA[o / 2 + 1] = fma2(w0.y, dA0, accA[o / 2 + 1]);
            accB[o / 2]     = fma2(w0.x, dB0, accB[o / 2]);
            accB[o / 2 + 1] = fma2(w0.y, dB0, accB[o / 2 + 1]);
            accA[o / 2]     = fma2(w1.x, dA1, accA[o / 2]);
            accA[o / 2 + 1] = fma2(w1.y, dA1, accA[o / 2 + 1]);
            accB[o / 2]     = fma2(w1.x, dB1, accB[o / 2]);
            accB[o / 2 + 1] = fma2(w1.y, dB1, accB[o / 2 + 1]);
        }
    }

    // collapse L4: add bias pair, relu — already feature-pair layout for L5
    u64 h4A[16], h4B[16];
    const u64* sb4p = reinterpret_cast<const u64*>(sB4);
    #pragma unroll
    for (int i = 0; i < 16; i++) {
        const u64 bp = sb4p[i];
        h4A[i] = relu2(add2(accA[i], bp));
        h4B[i] = relu2(add2(accB[i], bp));
    }

    // L5 -> element-packed q
    u64 qv[NJ];
    #pragma unroll
    for (int o = 0; o < 12; o += 2) {
        u64 aA0 = ZERO2, aA1 = ZERO2, bA0 = ZERO2, bA1 = ZERO2;
        u64 aB0 = ZERO2, aB1 = ZERO2, bB0 = ZERO2, bB1 = ZERO2;
        const float* r0 = sW5 + o * 32;
        const float* r1 = r0 + 32;
        #pragma unroll
        for (int k = 0; k < 32; k += 4) {
            const ulonglong2 w0 = *reinterpret_cast<const ulonglong2*>(r0 + k);
            const ulonglong2 w1 = *reinterpret_cast<const ulonglong2*>(r1 + k);
            const u64 hAa = h4A[k / 2], hAb = h4A[k / 2 + 1];
            const u64 hBa = h4B[k / 2], hBb = h4B[k / 2 + 1];
            aA0 = fma2(w0.x, hAa, aA0);  aA1 = fma2(w0.y, hAb, aA1);
            aB0 = fma2(w0.x, hBa, aB0);  aB1 = fma2(w0.y, hBb, aB1);
            bA0 = fma2(w1.x, hAa, bA0);  bA1 = fma2(w1.y, hAb, bA1);
            bB0 = fma2(w1.x, hBa, bB0);  bB1 = fma2(w1.y, hBb, bB1);
        }
        const float bo = sB5[o], bo1 = sB5[o + 1];
        qv[o]     = pack2(hsum_relu(add2(aA0, aA1), bo),
                          hsum_relu(add2(aB0, aB1), bo));
        qv[o + 1] = pack2(hsum_relu(add2(bA0, bA1), bo1),
                          hsum_relu(add2(bB0, bB1), bo1));
    }

    // ---- element-packed SE(3) chain ----
    u64 T[12] = { ONE2, ZERO2, ZERO2, ZERO2,
                  ZERO2, ONE2, ZERO2, ZERO2,
                  ZERO2, ZERO2, ONE2, ZERO2 };
    #pragma unroll
    for (int j = 0; j < NJ; j++) {
        const u64 th2 = mul2(qv[j], sjwn[j]);
        float th0, th1; unpack2(th2, th0, th1);
        float s0, co0, s1, co1;
        __sincosf(th0, &s0, &co0);
        __sincosf(th1, &s1, &co1);
        const u64 s2 = pack2(s0, s1);
        const u64 c2 = pack2(1.0f - co0, 1.0f - co1);
        const u64 t2 = pack2(th0 - s0, th1 - s1);

        u64 R[9];
        #pragma unroll
        for (int e = 0; e < 9; e++) {
            const u64 d = (e == 0 || e == 4 || e == 8) ? ONE2 : ZERO2;
            R[e] = fma2(s2, sjK[j][e], fma2(c2, sjK2[j][e], d));
        }
        const u64 p0 = fma2(th2, sjru[j][0], fma2(c2, sjKru[j][0], mul2(t2, sjK2ru[j][0])));
        const u64 p1 = fma2(th2, sjru[j][1], fma2(c2, sjKru[j][1], mul2(t2, sjK2ru[j][1])));
        const u64 p2 = fma2(th2, sjru[j][2], fma2(c2, sjKru[j][2], mul2(t2, sjK2ru[j][2])));

        u64 N[12];
        #pragma unroll
        for (int r = 0; r < 3; r++) {
            const u64 a0r = T[r*4+0], a1r = T[r*4+1], a2r = T[r*4+2], a3r = T[r*4+3];
            N[r*4+0] = fma2(a0r, R[0], fma2(a1r, R[3], mul2(a2r, R[6])));
            N[r*4+1] = fma2(a0r, R[1], fma2(a1r, R[4], mul2(a2r, R[7])));
            N[r*4+2] = fma2(a0r, R[2], fma2(a1r, R[5], mul2(a2r, R[8])));
            N[r*4+3] = fma2(a0r, p0,  fma2(a1r, p1,  fma2(a2r, p2, a3r)));
        }
        #pragma unroll
        for (int e = 0; e < 12; e++) T[e] = N[e];
    }

    float4* op0 = reinterpret_cast<float4*>(out + (size_t)i0 * 16);
    float4* op1 = reinterpret_cast<float4*>(out + (size_t)i1 * 16);
    #pragma unroll
    for (int r = 0; r < 3; r++) {
        const u64 a0r = T[r*4+0], a1r = T[r*4+1], a2r = T[r*4+2], a3r = T[r*4+3];
        const u64 vx = fma2(a0r, sT0[0], fma2(a1r, sT0[4], mul2(a2r, sT0[8])));
        const u64 vy = fma2(a0r, sT0[1], fma2(a1r, sT0[5], mul2(a2r, sT0[9])));
        const u64 vz = fma2(a0r, sT0[2], fma2(a1r, sT0[6], mul2(a2r, sT0[10])));
        const u64 vw = fma2(a0r, sT0[3], fma2(a1r, sT0[7], fma2(a2r, sT0[11], a3r)));
        float4 r0, r1;
        unpack2(vx, r0.x, r1.x);
        unpack2(vy, r0.y, r1.y);
        unpack2(vz, r0.z, r1.z);
        unpack2(vw, r0.w, r1.w);
        op0[r] = r0;
        op1[r] = r1;
    }
    op0[3] = make_float4(0.f, 0.f, 0.f, 1.f);
    op1[3] = make_float4(0.f, 0.f, 0.f, 1.f);
}

extern "C" void kernel_launch(void* const* d_in, const int* in_sizes, int n_in,
                              void* d_out, int out_size)
{
    const float* mc   = (const float*)d_in[0];
    const float* W1   = (const float*)d_in[1];
    const float* b1   = (const float*)d_in[2];
    const float* W2   = (const float*)d_in[3];
    const float* b2   = (const float*)d_in[4];
    const float* W3   = (const float*)d_in[5];
    const float* b3   = (const float*)d_in[6];
    const float* W4   = (const float*)d_in[7];
    const float* b4   = (const float*)d_in[8];
    const float* W5   = (const float*)d_in[9];
    const float* b5   = (const float*)d_in[10];
    const float* tw   = (const float*)d_in[11];
    const float* ip   = (const float*)d_in[12];
    const float* irpy = (const float*)d_in[13];
    float* out = (float*)d_out;

    const int B = in_sizes[0] / 4;
    const int elems_per_block = 2 * BLK;
    const int grid = (B + elems_per_block - 1) / elems_per_block;
    fk_kernel<<<grid, BLK>>>(mc, W1, b1, W2, b2, W3, b3, W4, b4, W5, b5,
                             tw, ip, irpy, out, B);
}